// round 10
// baseline (speedup 1.0000x reference)
#include <cuda_runtime.h>
#include <cuda_bf16.h>
#include <math_constants.h>

#define BB 8
#define NP 2048
#define KK 20
#define BN (BB*NP)
#define EPSV 1e-5f
#define SLOPEV 0.2f

// ---------------- scratch (device globals; no allocation allowed) ----------------
__device__ double g_xx[BN];
__device__ int    g_idx[BN*KK];
__device__ float  g_x1[BN*64];
__device__ float  g_x2[BN*64];
__device__ float  g_x3[BN*128];
__device__ float  g_x4[BN*256];
__device__ float  g_m[BN*256];      // per-point pre-BN max over k (reused per layer)
__device__ float  g_m5[BB*1024];    // per-batch pre-BN max over points
__device__ double g_sum[1024];
__device__ double g_sumsq[1024];

// ---------------- helpers ----------------
__device__ __forceinline__ unsigned long long knn_key(float v, unsigned j) {
    int i = __float_as_int(v);
    unsigned u = (i >= 0) ? ((unsigned)i | 0x80000000u) : ~((unsigned)i);
    // tie-break: lower index wins -> larger low word
    return ((unsigned long long)u << 32) | (unsigned long long)(0xFFFFFFFFu - j);
}

__device__ __forceinline__ void atomicMaxFloat(float* addr, float val) {
    int* ia = (int*)addr;
    int old = *ia;
    while (__int_as_float(old) < val) {
        int assumed = old;
        old = atomicCAS(ia, assumed, __float_as_int(val));
        if (old == assumed) break;
    }
}

// ---------------- reset kernels ----------------
__global__ void reset_stats_kernel() {
    int i = blockIdx.x * blockDim.x + threadIdx.x;
    if (i < 1024) { g_sum[i] = 0.0; g_sumsq[i] = 0.0; }
}

__global__ void reset_m5_kernel() {
    int i = blockIdx.x * blockDim.x + threadIdx.x;
    if (i < 1024) { g_sum[i] = 0.0; g_sumsq[i] = 0.0; }
    if (i < BB * 1024) g_m5[i] = -CUDART_INF_F;
}

// ---------------- squared norms in double (near-exact ranking inputs) ----------------
template<int C>
__global__ void xx_kernel(const float* __restrict__ x) {
    int p = blockIdx.x * blockDim.x + threadIdx.x;
    if (p >= BN) return;
    const float* r = x + (size_t)p * C;
    double s = 0.0;
    #pragma unroll 4
    for (int c = 0; c < C; c++) { double v = (double)r[c]; s = fma(v, v, s); }
    g_xx[p] = s;
}

// ---------------- knn: one block per query point, 256 threads ----------------
// inner products in DOUBLE (near-exact), then pd quantized to fp32 so
// tie-break semantics match the reference's fp32 top_k.
template<int C>
__global__ void knn_kernel(const float* __restrict__ x) {
    __shared__ __align__(16) float q[(C + 3) & ~3];
    __shared__ unsigned long long skey[256];
    const int tid = threadIdx.x;
    const int b = blockIdx.x / NP;
    const int n = blockIdx.x % NP;
    const float* xb = x + (size_t)b * NP * C;

    for (int c = tid; c < C; c += 256) q[c] = xb[(size_t)n * C + c];
    __syncthreads();

    const double xxi = g_xx[b * NP + n];
    const double* xxb = g_xx + b * NP;

    // 2048 candidates / 256 threads = 8 per thread
    unsigned long long key[8];
    #pragma unroll
    for (int t = 0; t < 8; t++) {
        int j = tid + t * 256;
        double dot = 0.0;
        if constexpr ((C & 3) == 0) {
            const float4* r4 = reinterpret_cast<const float4*>(xb + (size_t)j * C);
            const float4* q4 = reinterpret_cast<const float4*>(q);
            #pragma unroll 4
            for (int c = 0; c < C / 4; c++) {
                float4 rv = r4[c], qv = q4[c];
                dot = fma((double)qv.x, (double)rv.x, dot);
                dot = fma((double)qv.y, (double)rv.y, dot);
                dot = fma((double)qv.z, (double)rv.z, dot);
                dot = fma((double)qv.w, (double)rv.w, dot);
            }
        } else {
            const float* r = xb + (size_t)j * C;
            #pragma unroll
            for (int c = 0; c < C; c++) dot = fma((double)q[c], (double)r[c], dot);
        }
        float pd = (float)((2.0 * dot - xxi) - xxb[j]);
        key[t] = knn_key(pd, (unsigned)j);
    }
    // sort 8 keys descending (insertion sort)
    #pragma unroll
    for (int a = 1; a < 8; a++) {
        unsigned long long kk = key[a];
        int p2 = a - 1;
        while (p2 >= 0 && key[p2] < kk) { key[p2 + 1] = key[p2]; p2--; }
        key[p2 + 1] = kk;
    }

    int* out = g_idx + (size_t)(b * NP + n) * KK;
    int ptr = 0;
    for (int sel = 0; sel < KK; sel++) {
        skey[tid] = (ptr < 8) ? key[ptr] : 0ULL;
        __syncthreads();
        #pragma unroll
        for (int s = 128; s > 0; s >>= 1) {
            if (tid < s) {
                unsigned long long a2 = skey[tid], b2 = skey[tid + s];
                skey[tid] = (a2 > b2) ? a2 : b2;
            }
            __syncthreads();
        }
        unsigned long long w = skey[0];
        __syncthreads();
        if (ptr < 8 && key[ptr] == w) ptr++;
        if (tid == 0) out[sel] = (int)(0xFFFFFFFFu - (unsigned)(w & 0xFFFFFFFFull));
    }
}

// ---------------- edge conv: one block per point (plain fp32) ----------------
// h[k][o] = Wd[o]·(nb_k - xc) + Wx[o]·xc ; m = max_k h ; stats sums over all h
template<int C, int O, int TPB>
__global__ void conv_kernel(const float* __restrict__ xin, const float* __restrict__ W,
                            float* __restrict__ m) {
    __shared__ __align__(16) float xc[C];
    __shared__ __align__(16) float D[KK][C];
    __shared__ int nidx[KK];
    const int tid = threadIdx.x;
    const int b = blockIdx.x / NP;
    const int n = blockIdx.x % NP;
    const float* xb = xin + (size_t)b * NP * C;

    for (int c = tid; c < C; c += TPB) xc[c] = xb[(size_t)n * C + c];
    if (tid < KK) nidx[tid] = g_idx[(size_t)(b * NP + n) * KK + tid];
    __syncthreads();
    for (int e = tid; e < KK * C; e += TPB) {
        int k = e / C, c = e % C;
        D[k][c] = xb[(size_t)nidx[k] * C + c] - xc[c];
    }
    __syncthreads();

    for (int o = tid; o < O; o += TPB) {
        const float* wd = W + (size_t)o * 2 * C;
        const float* wx = wd + C;
        float cx = 0.f;
        #pragma unroll 4
        for (int c = 0; c < C; c++) cx += wx[c] * xc[c];
        float acc[KK];
        #pragma unroll
        for (int k = 0; k < KK; k++) acc[k] = cx;
        #pragma unroll 2
        for (int c = 0; c < C; c++) {
            float w = wd[c];
            #pragma unroll
            for (int k = 0; k < KK; k++) acc[k] += w * D[k][c];
        }
        float mv = -CUDART_INF_F;
        double s = 0.0, s2 = 0.0;
        #pragma unroll
        for (int k = 0; k < KK; k++) {
            mv = fmaxf(mv, acc[k]);
            s += (double)acc[k];
            s2 += (double)acc[k] * (double)acc[k];
        }
        m[(size_t)(b * NP + n) * O + o] = mv;
        atomicAdd(&g_sum[o], s);
        atomicAdd(&g_sumsq[o], s2);
    }
}

// ---------------- post: xout = lrelu(bn(m)) ----------------
template<int O>
__global__ void post_kernel(const float* __restrict__ m, const float* __restrict__ gamma,
                            const float* __restrict__ beta, float* __restrict__ xout,
                            double Minv) {
    int i = blockIdx.x * blockDim.x + threadIdx.x;
    if (i >= BN * O) return;
    int o = i % O;
    double mean = g_sum[o] * Minv;
    double var = g_sumsq[o] * Minv - mean * mean;
    float scale = (float)(1.0 / sqrt(var + (double)EPSV));
    float h = ((m[i] - (float)mean) * scale) * gamma[o] + beta[o];
    xout[i] = (h >= 0.f) ? h : SLOPEV * h;
}

// ---------------- conv5: 8 points per block, O=1024, Cin=512 (fp32) ----------------
__global__ void conv5_kernel(const float* __restrict__ W5) {
    __shared__ __align__(16) float sx[8][512];
    const int tid = threadIdx.x;
    const int b = blockIdx.x / (NP / 8);
    const int n0 = (blockIdx.x % (NP / 8)) * 8;

    for (int e = tid; e < 8 * 512; e += 256) {
        int p = e >> 9, c = e & 511;
        size_t pn = (size_t)b * NP + n0 + p;
        float v;
        if (c < 64)       v = g_x1[pn * 64 + c];
        else if (c < 128) v = g_x2[pn * 64 + (c - 64)];
        else if (c < 256) v = g_x3[pn * 128 + (c - 128)];
        else              v = g_x4[pn * 256 + (c - 256)];
        sx[p][c] = v;
    }
    __syncthreads();

    #pragma unroll
    for (int j = 0; j < 4; j++) {
        int o = tid + j * 256;
        const float4* w4 = reinterpret_cast<const float4*>(W5 + (size_t)o * 512);
        float acc[8] = {0.f, 0.f, 0.f, 0.f, 0.f, 0.f, 0.f, 0.f};
        #pragma unroll 4
        for (int c4 = 0; c4 < 128; c4++) {
            float4 wv = w4[c4];
            int c = c4 * 4;
            #pragma unroll
            for (int p = 0; p < 8; p++) {
                acc[p] += wv.x * sx[p][c] + wv.y * sx[p][c + 1]
                        + wv.z * sx[p][c + 2] + wv.w * sx[p][c + 3];
            }
        }
        double s = 0.0, s2 = 0.0;
        float mv = -CUDART_INF_F;
        #pragma unroll
        for (int p = 0; p < 8; p++) {
            s += (double)acc[p]; s2 += (double)acc[p] * (double)acc[p];
            mv = fmaxf(mv, acc[p]);
        }
        atomicAdd(&g_sum[o], s);
        atomicAdd(&g_sumsq[o], s2);
        atomicMaxFloat(&g_m5[b * 1024 + o], mv);
    }
}

// ---------------- final: out[b][o] = lrelu(bn(max_n h5)) ----------------
__global__ void final_kernel(const float* __restrict__ g5, const float* __restrict__ b5,
                             float* __restrict__ out) {
    int b = blockIdx.x;
    int o = threadIdx.x;
    const double Minv = 1.0 / (double)(BB * NP);
    double mean = g_sum[o] * Minv;
    double var = g_sumsq[o] * Minv - mean * mean;
    float scale = (float)(1.0 / sqrt(var + (double)EPSV));
    float h = ((g_m5[b * 1024 + o] - (float)mean) * scale) * g5[o] + b5[o];
    out[b * 1024 + o] = (h >= 0.f) ? h : SLOPEV * h;
}

// ---------------- launch ----------------
extern "C" void kernel_launch(void* const* d_in, const int* in_sizes, int n_in,
                              void* d_out, int out_size) {
    const float* x  = (const float*)d_in[0];
    const float* W1 = (const float*)d_in[1];
    const float* g1 = (const float*)d_in[2];
    const float* b1 = (const float*)d_in[3];
    const float* W2 = (const float*)d_in[4];
    const float* g2 = (const float*)d_in[5];
    const float* b2 = (const float*)d_in[6];
    const float* W3 = (const float*)d_in[7];
    const float* g3 = (const float*)d_in[8];
    const float* b3 = (const float*)d_in[9];
    const float* W4 = (const float*)d_in[10];
    const float* g4 = (const float*)d_in[11];
    const float* b4 = (const float*)d_in[12];
    const float* W5 = (const float*)d_in[13];
    const float* g5 = (const float*)d_in[14];
    const float* b5 = (const float*)d_in[15];
    float* out = (float*)d_out;

    const double MinvK = 1.0 / (double)(BB * NP * KK);

    float *d_m, *d_x1, *d_x2, *d_x3, *d_x4;
    cudaGetSymbolAddress((void**)&d_m, g_m);
    cudaGetSymbolAddress((void**)&d_x1, g_x1);
    cudaGetSymbolAddress((void**)&d_x2, g_x2);
    cudaGetSymbolAddress((void**)&d_x3, g_x3);
    cudaGetSymbolAddress((void**)&d_x4, g_x4);

    // ---- Layer 1 (C=3 -> O=64) ----
    reset_stats_kernel<<<4, 256>>>();
    xx_kernel<3><<<BN / 256, 256>>>(x);
    knn_kernel<3><<<BN, 256>>>(x);
    conv_kernel<3, 64, 128><<<BN, 128>>>(x, W1, d_m);
    post_kernel<64><<<(BN * 64) / 256, 256>>>(d_m, g1, b1, d_x1, MinvK);

    // ---- Layer 2 (C=64 -> O=64) ----
    reset_stats_kernel<<<4, 256>>>();
    xx_kernel<64><<<BN / 256, 256>>>(d_x1);
    knn_kernel<64><<<BN, 256>>>(d_x1);
    conv_kernel<64, 64, 128><<<BN, 128>>>(d_x1, W2, d_m);
    post_kernel<64><<<(BN * 64) / 256, 256>>>(d_m, g2, b2, d_x2, MinvK);

    // ---- Layer 3 (C=64 -> O=128) ----
    reset_stats_kernel<<<4, 256>>>();
    xx_kernel<64><<<BN / 256, 256>>>(d_x2);
    knn_kernel<64><<<BN, 256>>>(d_x2);
    conv_kernel<64, 128, 128><<<BN, 128>>>(d_x2, W3, d_m);
    post_kernel<128><<<(BN * 128) / 256, 256>>>(d_m, g3, b3, d_x3, MinvK);

    // ---- Layer 4 (C=128 -> O=256) ----
    reset_stats_kernel<<<4, 256>>>();
    xx_kernel<128><<<BN / 256, 256>>>(d_x3);
    knn_kernel<128><<<BN, 256>>>(d_x3);
    conv_kernel<128, 256, 256><<<BN, 256>>>(d_x3, W4, d_m);
    post_kernel<256><<<(BN * 256) / 256, 256>>>(d_m, g4, b4, d_x4, MinvK);

    // ---- conv5 + global max ----
    reset_m5_kernel<<<32, 256>>>();
    conv5_kernel<<<BB * (NP / 8), 256>>>(W5);
    final_kernel<<<BB, 1024>>>(g5, b5, out);
}

// round 11
// speedup vs baseline: 1.0339x; 1.0339x over previous
#include <cuda_runtime.h>
#include <cuda_bf16.h>
#include <math_constants.h>

#define BB 8
#define NP 2048
#define KK 20
#define BN (BB*NP)
#define EPSV 1e-5f
#define SLOPEV 0.2f

// ---------------- scratch (device globals; no allocation allowed) ----------------
__device__ float2 g_xx[BN];        // hi/lo split of squared norms
__device__ int    g_idx[BN*KK];
__device__ float  g_x1[BN*64];
__device__ float  g_x2[BN*64];
__device__ float  g_x3[BN*128];
__device__ float  g_x4[BN*256];
__device__ float  g_m[BN*256];
__device__ float  g_m5[BB*1024];
__device__ double g_sum[1024];
__device__ double g_sumsq[1024];

// ---------------- helpers ----------------
__device__ __forceinline__ unsigned long long knn_key(float v, unsigned j) {
    int i = __float_as_int(v);
    unsigned u = (i >= 0) ? ((unsigned)i | 0x80000000u) : ~((unsigned)i);
    return ((unsigned long long)u << 32) | (unsigned long long)(0xFFFFFFFFu - j);
}

__device__ __forceinline__ void atomicMaxFloat(float* addr, float val) {
    int* ia = (int*)addr;
    int old = *ia;
    while (__int_as_float(old) < val) {
        int assumed = old;
        old = atomicCAS(ia, assumed, __float_as_int(val));
        if (old == assumed) break;
    }
}

// exact twoSum (Knuth), rounding-mode-pinned so no contraction/reassoc
__device__ __forceinline__ void two_sum(float a, float b, float& s, float& e) {
    s = __fadd_rn(a, b);
    float bb = __fsub_rn(s, a);
    e = __fadd_rn(__fsub_rn(a, __fsub_rn(s, bb)), __fsub_rn(b, bb));
}

// Kahan + exact-product step: sa/ca = Kahan state for hi parts, ea = product-error sum
__device__ __forceinline__ void kah(float a, float b, float& sa, float& ca, float& ea) {
    float p = __fmul_rn(a, b);
    ea = __fadd_rn(ea, __fmaf_rn(a, b, -p));
    float y = __fsub_rn(p, ca);
    float t = __fadd_rn(sa, y);
    ca = __fsub_rn(__fsub_rn(t, sa), y);
    sa = t;
}

// ---------------- reset kernels ----------------
__global__ void reset_stats_kernel() {
    int i = blockIdx.x * blockDim.x + threadIdx.x;
    if (i < 1024) { g_sum[i] = 0.0; g_sumsq[i] = 0.0; }
}

__global__ void reset_m5_kernel() {
    int i = blockIdx.x * blockDim.x + threadIdx.x;
    if (i < 1024) { g_sum[i] = 0.0; g_sumsq[i] = 0.0; }
    if (i < BB * 1024) g_m5[i] = -CUDART_INF_F;
}

// ---------------- squared norms: double compute, hi/lo split store ----------------
template<int C>
__global__ void xx_kernel(const float* __restrict__ x) {
    int p = blockIdx.x * blockDim.x + threadIdx.x;
    if (p >= BN) return;
    const float* r = x + (size_t)p * C;
    double s = 0.0;
    #pragma unroll 4
    for (int c = 0; c < C; c++) { double v = (double)r[c]; s = fma(v, v, s); }
    float hi = (float)s;
    float lo = (float)(s - (double)hi);
    g_xx[p] = make_float2(hi, lo);
}

// ---------------- knn: one block per query point, 256 threads ----------------
// df64 (Kahan-compensated fp32) inner products -> near-exact pd -> fp32 quantize -> rank
template<int C>
__global__ void knn_kernel(const float* __restrict__ x) {
    __shared__ __align__(16) float q[(C + 3) & ~3];
    __shared__ unsigned long long swarp[8];
    __shared__ unsigned long long swin_s;
    const int tid = threadIdx.x;
    const int lane = tid & 31, warp = tid >> 5;
    const int b = blockIdx.x / NP;
    const int n = blockIdx.x % NP;
    const float* xb = x + (size_t)b * NP * C;

    for (int c = tid; c < C; c += 256) q[c] = xb[(size_t)n * C + c];
    __syncthreads();

    const float2 xxi = g_xx[b * NP + n];
    const float2* xxb = g_xx + b * NP;

    unsigned long long key[8];
    #pragma unroll
    for (int t = 0; t < 8; t++) {
        int j = tid + t * 256;
        float pd;
        if constexpr (C == 3) {
            const float* r = xb + (size_t)j * 3;
            double dot = fma((double)q[0], (double)r[0],
                         fma((double)q[1], (double)r[1],
                             (double)q[2] * (double)r[2]));
            double xi = (double)xxi.x + (double)xxi.y;
            float2 xjf = xxb[j];
            double xj = (double)xjf.x + (double)xjf.y;
            pd = (float)((2.0 * dot - xi) - xj);
        } else {
            const float4* r4 = reinterpret_cast<const float4*>(xb + (size_t)j * C);
            const float4* q4 = reinterpret_cast<const float4*>(q);
            float s0 = 0.f, s1 = 0.f, s2 = 0.f, s3 = 0.f;
            float c0 = 0.f, c1 = 0.f, c2 = 0.f, c3 = 0.f;
            float e0 = 0.f, e1 = 0.f, e2 = 0.f, e3 = 0.f;
            #pragma unroll 4
            for (int c = 0; c < C / 4; c++) {
                float4 rv = r4[c], qv = q4[c];
                kah(qv.x, rv.x, s0, c0, e0);
                kah(qv.y, rv.y, s1, c1, e1);
                kah(qv.z, rv.z, s2, c2, e2);
                kah(qv.w, rv.w, s3, c3, e3);
            }
            // merge 4 Kahan partials into df (H, L)
            float h01, l01, h23, l23, H, L;
            two_sum(s0, s1, h01, l01);
            two_sum(s2, s3, h23, l23);
            two_sum(h01, h23, H, L);
            float elo = __fadd_rn(__fadd_rn(__fadd_rn(e0, e1), __fadd_rn(e2, e3)),
                        __fsub_rn(__fadd_rn(__fadd_rn(l01, l23), L),
                                  __fadd_rn(__fadd_rn(c0, c1), __fadd_rn(c2, c3))));
            // pd = 2*dot - xxi - xxj in df arithmetic
            float th = __fmul_rn(2.0f, H);     // exact
            float tl = __fmul_rn(2.0f, elo);   // exact
            float2 xjf = xxb[j];
            float sA, eA;
            two_sum(th, -xxi.x, sA, eA);
            eA = __fadd_rn(eA, __fsub_rn(tl, xxi.y));
            float th2 = __fadd_rn(sA, eA);
            float tl2 = __fsub_rn(eA, __fsub_rn(th2, sA));
            float sB, eB;
            two_sum(th2, -xjf.x, sB, eB);
            eB = __fadd_rn(eB, __fsub_rn(tl2, xjf.y));
            pd = __fadd_rn(sB, eB);
        }
        key[t] = knn_key(pd, (unsigned)j);
    }

    // sort 8 keys descending (insertion sort)
    #pragma unroll
    for (int a = 1; a < 8; a++) {
        unsigned long long kk = key[a];
        int p2 = a - 1;
        while (p2 >= 0 && key[p2] < kk) { key[p2 + 1] = key[p2]; p2--; }
        key[p2 + 1] = kk;
    }

    // top-20 selection: warp-shuffle tournament, 2 barriers per round
    int* out = g_idx + (size_t)(b * NP + n) * KK;
    int ptr = 0;
    for (int sel = 0; sel < KK; sel++) {
        unsigned long long vv = (ptr < 8) ? key[ptr] : 0ULL;
        #pragma unroll
        for (int s = 16; s > 0; s >>= 1) {
            unsigned long long o = __shfl_down_sync(0xFFFFFFFFu, vv, s);
            vv = (o > vv) ? o : vv;
        }
        if (lane == 0) swarp[warp] = vv;
        __syncthreads();
        if (warp == 0) {
            unsigned long long m = (lane < 8) ? swarp[lane] : 0ULL;
            #pragma unroll
            for (int s = 4; s > 0; s >>= 1) {
                unsigned long long o = __shfl_down_sync(0xFFFFFFFFu, m, s);
                m = (o > m) ? o : m;
            }
            if (lane == 0) {
                swin_s = m;
                out[sel] = (int)(0xFFFFFFFFu - (unsigned)(m & 0xFFFFFFFFull));
            }
        }
        __syncthreads();
        unsigned long long w = swin_s;
        if (ptr < 8 && key[ptr] == w) ptr++;
    }
}

// ---------------- edge conv: one block per point (plain fp32) ----------------
template<int C, int O, int TPB>
__global__ void conv_kernel(const float* __restrict__ xin, const float* __restrict__ W,
                            float* __restrict__ m) {
    __shared__ __align__(16) float xc[C];
    __shared__ __align__(16) float D[KK][C];
    __shared__ int nidx[KK];
    const int tid = threadIdx.x;
    const int b = blockIdx.x / NP;
    const int n = blockIdx.x % NP;
    const float* xb = xin + (size_t)b * NP * C;

    for (int c = tid; c < C; c += TPB) xc[c] = xb[(size_t)n * C + c];
    if (tid < KK) nidx[tid] = g_idx[(size_t)(b * NP + n) * KK + tid];
    __syncthreads();
    for (int e = tid; e < KK * C; e += TPB) {
        int k = e / C, c = e % C;
        D[k][c] = xb[(size_t)nidx[k] * C + c] - xc[c];
    }
    __syncthreads();

    for (int o = tid; o < O; o += TPB) {
        const float* wd = W + (size_t)o * 2 * C;
        const float* wx = wd + C;
        float cx = 0.f;
        #pragma unroll 4
        for (int c = 0; c < C; c++) cx += wx[c] * xc[c];
        float acc[KK];
        #pragma unroll
        for (int k = 0; k < KK; k++) acc[k] = cx;
        #pragma unroll 2
        for (int c = 0; c < C; c++) {
            float w = wd[c];
            #pragma unroll
            for (int k = 0; k < KK; k++) acc[k] += w * D[k][c];
        }
        float mv = -CUDART_INF_F;
        double s = 0.0, s2 = 0.0;
        #pragma unroll
        for (int k = 0; k < KK; k++) {
            mv = fmaxf(mv, acc[k]);
            s += (double)acc[k];
            s2 += (double)acc[k] * (double)acc[k];
        }
        m[(size_t)(b * NP + n) * O + o] = mv;
        atomicAdd(&g_sum[o], s);
        atomicAdd(&g_sumsq[o], s2);
    }
}

// ---------------- post: xout = lrelu(bn(m)) ----------------
template<int O>
__global__ void post_kernel(const float* __restrict__ m, const float* __restrict__ gamma,
                            const float* __restrict__ beta, float* __restrict__ xout,
                            double Minv) {
    int i = blockIdx.x * blockDim.x + threadIdx.x;
    if (i >= BN * O) return;
    int o = i % O;
    double mean = g_sum[o] * Minv;
    double var = g_sumsq[o] * Minv - mean * mean;
    float scale = (float)(1.0 / sqrt(var + (double)EPSV));
    float h = ((m[i] - (float)mean) * scale) * gamma[o] + beta[o];
    xout[i] = (h >= 0.f) ? h : SLOPEV * h;
}

// ---------------- conv5: 8 points per block, O=1024, Cin=512 (fp32) ----------------
__global__ void conv5_kernel(const float* __restrict__ W5) {
    __shared__ __align__(16) float sx[8][512];
    const int tid = threadIdx.x;
    const int b = blockIdx.x / (NP / 8);
    const int n0 = (blockIdx.x % (NP / 8)) * 8;

    for (int e = tid; e < 8 * 512; e += 256) {
        int p = e >> 9, c = e & 511;
        size_t pn = (size_t)b * NP + n0 + p;
        float v;
        if (c < 64)       v = g_x1[pn * 64 + c];
        else if (c < 128) v = g_x2[pn * 64 + (c - 64)];
        else if (c < 256) v = g_x3[pn * 128 + (c - 128)];
        else              v = g_x4[pn * 256 + (c - 256)];
        sx[p][c] = v;
    }
    __syncthreads();

    #pragma unroll
    for (int j = 0; j < 4; j++) {
        int o = tid + j * 256;
        const float4* w4 = reinterpret_cast<const float4*>(W5 + (size_t)o * 512);
        float acc[8] = {0.f, 0.f, 0.f, 0.f, 0.f, 0.f, 0.f, 0.f};
        #pragma unroll 4
        for (int c4 = 0; c4 < 128; c4++) {
            float4 wv = w4[c4];
            int c = c4 * 4;
            #pragma unroll
            for (int p = 0; p < 8; p++) {
                acc[p] += wv.x * sx[p][c] + wv.y * sx[p][c + 1]
                        + wv.z * sx[p][c + 2] + wv.w * sx[p][c + 3];
            }
        }
        double s = 0.0, s2 = 0.0;
        float mv = -CUDART_INF_F;
        #pragma unroll
        for (int p = 0; p < 8; p++) {
            s += (double)acc[p]; s2 += (double)acc[p] * (double)acc[p];
            mv = fmaxf(mv, acc[p]);
        }
        atomicAdd(&g_sum[o], s);
        atomicAdd(&g_sumsq[o], s2);
        atomicMaxFloat(&g_m5[b * 1024 + o], mv);
    }
}

// ---------------- final: out[b][o] = lrelu(bn(max_n h5)) ----------------
__global__ void final_kernel(const float* __restrict__ g5, const float* __restrict__ b5,
                             float* __restrict__ out) {
    int b = blockIdx.x;
    int o = threadIdx.x;
    const double Minv = 1.0 / (double)(BB * NP);
    double mean = g_sum[o] * Minv;
    double var = g_sumsq[o] * Minv - mean * mean;
    float scale = (float)(1.0 / sqrt(var + (double)EPSV));
    float h = ((g_m5[b * 1024 + o] - (float)mean) * scale) * g5[o] + b5[o];
    out[b * 1024 + o] = (h >= 0.f) ? h : SLOPEV * h;
}

// ---------------- launch ----------------
extern "C" void kernel_launch(void* const* d_in, const int* in_sizes, int n_in,
                              void* d_out, int out_size) {
    const float* x  = (const float*)d_in[0];
    const float* W1 = (const float*)d_in[1];
    const float* g1 = (const float*)d_in[2];
    const float* b1 = (const float*)d_in[3];
    const float* W2 = (const float*)d_in[4];
    const float* g2 = (const float*)d_in[5];
    const float* b2 = (const float*)d_in[6];
    const float* W3 = (const float*)d_in[7];
    const float* g3 = (const float*)d_in[8];
    const float* b3 = (const float*)d_in[9];
    const float* W4 = (const float*)d_in[10];
    const float* g4 = (const float*)d_in[11];
    const float* b4 = (const float*)d_in[12];
    const float* W5 = (const float*)d_in[13];
    const float* g5 = (const float*)d_in[14];
    const float* b5 = (const float*)d_in[15];
    float* out = (float*)d_out;

    const double MinvK = 1.0 / (double)(BB * NP * KK);

    float *d_m, *d_x1, *d_x2, *d_x3, *d_x4;
    cudaGetSymbolAddress((void**)&d_m, g_m);
    cudaGetSymbolAddress((void**)&d_x1, g_x1);
    cudaGetSymbolAddress((void**)&d_x2, g_x2);
    cudaGetSymbolAddress((void**)&d_x3, g_x3);
    cudaGetSymbolAddress((void**)&d_x4, g_x4);

    // ---- Layer 1 (C=3 -> O=64) ----
    reset_stats_kernel<<<4, 256>>>();
    xx_kernel<3><<<BN / 256, 256>>>(x);
    knn_kernel<3><<<BN, 256>>>(x);
    conv_kernel<3, 64, 128><<<BN, 128>>>(x, W1, d_m);
    post_kernel<64><<<(BN * 64) / 256, 256>>>(d_m, g1, b1, d_x1, MinvK);

    // ---- Layer 2 (C=64 -> O=64) ----
    reset_stats_kernel<<<4, 256>>>();
    xx_kernel<64><<<BN / 256, 256>>>(d_x1);
    knn_kernel<64><<<BN, 256>>>(d_x1);
    conv_kernel<64, 64, 128><<<BN, 128>>>(d_x1, W2, d_m);
    post_kernel<64><<<(BN * 64) / 256, 256>>>(d_m, g2, b2, d_x2, MinvK);

    // ---- Layer 3 (C=64 -> O=128) ----
    reset_stats_kernel<<<4, 256>>>();
    xx_kernel<64><<<BN / 256, 256>>>(d_x2);
    knn_kernel<64><<<BN, 256>>>(d_x2);
    conv_kernel<64, 128, 128><<<BN, 128>>>(d_x2, W3, d_m);
    post_kernel<128><<<(BN * 128) / 256, 256>>>(d_m, g3, b3, d_x3, MinvK);

    // ---- Layer 4 (C=128 -> O=256) ----
    reset_stats_kernel<<<4, 256>>>();
    xx_kernel<128><<<BN / 256, 256>>>(d_x3);
    knn_kernel<128><<<BN, 256>>>(d_x3);
    conv_kernel<128, 256, 256><<<BN, 256>>>(d_x3, W4, d_m);
    post_kernel<256><<<(BN * 256) / 256, 256>>>(d_m, g4, b4, d_x4, MinvK);

    // ---- conv5 + global max ----
    reset_m5_kernel<<<32, 256>>>();
    conv5_kernel<<<BB * (NP / 8), 256>>>(W5);
    final_kernel<<<BB, 1024>>>(g5, b5, out);
}

// round 12
// speedup vs baseline: 2.7497x; 2.6596x over previous
#include <cuda_runtime.h>
#include <cuda_bf16.h>
#include <math_constants.h>

#define BB 8
#define NP 2048
#define KK 20
#define BN (BB*NP)
#define EPSV 1e-5f
#define SLOPEV 0.2f

// ---------------- scratch (device globals; no allocation allowed) ----------------
__device__ float2 g_xx[BN];          // hi/lo split of squared norms
__device__ int    g_idx[BN*KK];
__device__ float  g_pd[(size_t)BN*NP];   // pairwise -dist^2 (fp32-quantized), 134MB
__device__ float  g_x1[BN*64];
__device__ float  g_x2[BN*64];
__device__ float  g_x3[BN*128];
__device__ float  g_x4[BN*256];
__device__ float  g_m[BN*256];
__device__ float  g_m5[BB*1024];
__device__ double g_sum[1024];
__device__ double g_sumsq[1024];
// transposed weights
__device__ float  g_W1t[6*64];
__device__ float  g_W2t[128*64];
__device__ float  g_W3t[128*128];
__device__ float  g_W4t[256*256];
__device__ float  g_W5t[512*1024];

// ---------------- helpers ----------------
__device__ __forceinline__ unsigned long long knn_key(float v, unsigned j) {
    int i = __float_as_int(v);
    unsigned u = (i >= 0) ? ((unsigned)i | 0x80000000u) : ~((unsigned)i);
    return ((unsigned long long)u << 32) | (unsigned long long)(0xFFFFFFFFu - j);
}

__device__ __forceinline__ void atomicMaxFloat(float* addr, float val) {
    int* ia = (int*)addr;
    int old = *ia;
    while (__int_as_float(old) < val) {
        int assumed = old;
        old = atomicCAS(ia, assumed, __float_as_int(val));
        if (old == assumed) break;
    }
}

__device__ __forceinline__ void two_sum(float a, float b, float& s, float& e) {
    s = __fadd_rn(a, b);
    float bb = __fsub_rn(s, a);
    e = __fadd_rn(__fsub_rn(a, __fsub_rn(s, bb)), __fsub_rn(b, bb));
}

// Kahan + exact-product step
__device__ __forceinline__ void kah(float a, float b, float& sa, float& ca, float& ea) {
    float p = __fmul_rn(a, b);
    ea = __fadd_rn(ea, __fmaf_rn(a, b, -p));
    float y = __fsub_rn(p, ca);
    float t = __fadd_rn(sa, y);
    ca = __fsub_rn(__fsub_rn(t, sa), y);
    sa = t;
}

// ---------------- transpose: out[c*O+o] = in[o*I+c] ----------------
__global__ void transpose_kernel(const float* __restrict__ in, float* __restrict__ out,
                                 int O, int I) {
    int idx = blockIdx.x * blockDim.x + threadIdx.x;
    if (idx >= O * I) return;
    int o = idx / I, c = idx % I;
    out[c * O + o] = in[idx];
}

// ---------------- reset kernels ----------------
__global__ void reset_stats_kernel() {
    int i = blockIdx.x * blockDim.x + threadIdx.x;
    if (i < 1024) { g_sum[i] = 0.0; g_sumsq[i] = 0.0; }
}

__global__ void reset_m5_kernel() {
    int i = blockIdx.x * blockDim.x + threadIdx.x;
    if (i < 1024) { g_sum[i] = 0.0; g_sumsq[i] = 0.0; }
    if (i < BB * 1024) g_m5[i] = -CUDART_INF_F;
}

// ---------------- squared norms: double compute, hi/lo split store ----------------
template<int C>
__global__ void xx_kernel(const float* __restrict__ x) {
    int p = blockIdx.x * blockDim.x + threadIdx.x;
    if (p >= BN) return;
    const float* r = x + (size_t)p * C;
    double s = 0.0;
    #pragma unroll 4
    for (int c = 0; c < C; c++) { double v = (double)r[c]; s = fma(v, v, s); }
    float hi = (float)s;
    float lo = (float)(s - (double)hi);
    g_xx[p] = make_float2(hi, lo);
}

// ---------------- pd kernel: tiled, Kahan-compensated fp32 ----------------
// block: 64 queries (blockIdx.x) of batch blockIdx.y; loops 64-candidate tiles.
// thread (ty,tx) in 16x16 grid owns 4 queries x 4 candidates.
template<int C>
__global__ __launch_bounds__(256) void pd_kernel(const float* __restrict__ x) {
    constexpr int CK = 64, CP = CK + 4;
    __shared__ __align__(16) float sQ[64][CP];
    __shared__ __align__(16) float sC[64][CP];
    const int tid = threadIdx.x;
    const int ty = tid >> 4, tx = tid & 15;
    const int b = blockIdx.y;
    const int q0 = blockIdx.x * 64;
    const float* xb = x + (size_t)b * NP * C;

    float2 xq[4];
    #pragma unroll
    for (int i = 0; i < 4; i++) xq[i] = g_xx[b * NP + q0 + ty * 4 + i];

    for (int jt = 0; jt < NP / 64; jt++) {
        float sa[16], ca[16], ea[16];
        #pragma unroll
        for (int a = 0; a < 16; a++) { sa[a] = 0.f; ca[a] = 0.f; ea[a] = 0.f; }

        #pragma unroll
        for (int ch = 0; ch < C / CK; ch++) {
            __syncthreads();
            for (int idx = tid; idx < 64 * CK; idx += 256) {
                int row = idx >> 6, col = idx & 63;
                sQ[row][col] = xb[(size_t)(q0 + row) * C + ch * CK + col];
                sC[row][col] = xb[(size_t)(jt * 64 + row) * C + ch * CK + col];
            }
            __syncthreads();
            for (int cc = 0; cc < CK; cc += 4) {
                float4 qv[4], cv[4];
                #pragma unroll
                for (int i = 0; i < 4; i++) {
                    qv[i] = *reinterpret_cast<const float4*>(&sQ[ty * 4 + i][cc]);
                    cv[i] = *reinterpret_cast<const float4*>(&sC[tx * 4 + i][cc]);
                }
                #pragma unroll
                for (int i = 0; i < 4; i++) {
                    #pragma unroll
                    for (int j2 = 0; j2 < 4; j2++) {
                        int a = i * 4 + j2;
                        kah(qv[i].x, cv[j2].x, sa[a], ca[a], ea[a]);
                        kah(qv[i].y, cv[j2].y, sa[a], ca[a], ea[a]);
                        kah(qv[i].z, cv[j2].z, sa[a], ca[a], ea[a]);
                        kah(qv[i].w, cv[j2].w, sa[a], ca[a], ea[a]);
                    }
                }
            }
        }
        // finalize + write
        #pragma unroll
        for (int j2 = 0; j2 < 4; j2++) {
            float2 xj = g_xx[b * NP + jt * 64 + tx * 4 + j2];
            #pragma unroll
            for (int i = 0; i < 4; i++) {
                int a = i * 4 + j2;
                float hi = sa[a];
                float lo = __fsub_rn(ea[a], ca[a]);
                float th = __fmul_rn(2.f, hi), tl = __fmul_rn(2.f, lo);
                float sA, eA;
                two_sum(th, -xq[i].x, sA, eA);
                eA = __fadd_rn(eA, __fsub_rn(tl, xq[i].y));
                float th2 = __fadd_rn(sA, eA);
                float tl2 = __fsub_rn(eA, __fsub_rn(th2, sA));
                float sB, eB;
                two_sum(th2, -xj.x, sB, eB);
                eB = __fadd_rn(eB, __fsub_rn(tl2, xj.y));
                float pd = __fadd_rn(sB, eB);
                g_pd[(size_t)(b * NP + q0 + ty * 4 + i) * NP + jt * 64 + tx * 4 + j2] = pd;
            }
        }
    }
}

// ---------------- topk: one block per query, reads coalesced pd row ----------------
__global__ void topk_kernel() {
    __shared__ unsigned long long swarp[8];
    __shared__ unsigned long long swin_s;
    const int tid = threadIdx.x;
    const int lane = tid & 31, warp = tid >> 5;
    const int pq = blockIdx.x;
    const float* pdrow = g_pd + (size_t)pq * NP;

    unsigned long long key[8];
    #pragma unroll
    for (int t = 0; t < 8; t++) {
        int j = tid + t * 256;
        key[t] = knn_key(pdrow[j], (unsigned)j);
    }
    #pragma unroll
    for (int a = 1; a < 8; a++) {
        unsigned long long kk = key[a];
        int p2 = a - 1;
        while (p2 >= 0 && key[p2] < kk) { key[p2 + 1] = key[p2]; p2--; }
        key[p2 + 1] = kk;
    }

    int* out = g_idx + (size_t)pq * KK;
    int ptr = 0;
    for (int sel = 0; sel < KK; sel++) {
        unsigned long long vv = (ptr < 8) ? key[ptr] : 0ULL;
        #pragma unroll
        for (int s = 16; s > 0; s >>= 1) {
            unsigned long long o = __shfl_down_sync(0xFFFFFFFFu, vv, s);
            vv = (o > vv) ? o : vv;
        }
        if (lane == 0) swarp[warp] = vv;
        __syncthreads();
        if (warp == 0) {
            unsigned long long m = (lane < 8) ? swarp[lane] : 0ULL;
            #pragma unroll
            for (int s = 4; s > 0; s >>= 1) {
                unsigned long long o = __shfl_down_sync(0xFFFFFFFFu, m, s);
                m = (o > m) ? o : m;
            }
            if (lane == 0) {
                swin_s = m;
                out[sel] = (int)(0xFFFFFFFFu - (unsigned)(m & 0xFFFFFFFFull));
            }
        }
        __syncthreads();
        unsigned long long w = swin_s;
        if (ptr < 8 && key[ptr] == w) ptr++;
    }
}

// ---------------- layer-1 knn (C=3, direct; tiny traffic) ----------------
__global__ void knn3_kernel(const float* __restrict__ x) {
    __shared__ unsigned long long swarp[8];
    __shared__ unsigned long long swin_s;
    const int tid = threadIdx.x;
    const int lane = tid & 31, warp = tid >> 5;
    const int b = blockIdx.x / NP;
    const int n = blockIdx.x % NP;
    const float* xb = x + (size_t)b * NP * 3;

    float q0 = xb[(size_t)n * 3 + 0], q1 = xb[(size_t)n * 3 + 1], q2 = xb[(size_t)n * 3 + 2];
    float2 xxi = g_xx[b * NP + n];
    const float2* xxb = g_xx + b * NP;

    unsigned long long key[8];
    #pragma unroll
    for (int t = 0; t < 8; t++) {
        int j = tid + t * 256;
        const float* r = xb + (size_t)j * 3;
        double dot = fma((double)q0, (double)r[0],
                     fma((double)q1, (double)r[1], (double)q2 * (double)r[2]));
        double xi = (double)xxi.x + (double)xxi.y;
        float2 xjf = xxb[j];
        double xj = (double)xjf.x + (double)xjf.y;
        float pd = (float)((2.0 * dot - xi) - xj);
        key[t] = knn_key(pd, (unsigned)j);
    }
    #pragma unroll
    for (int a = 1; a < 8; a++) {
        unsigned long long kk = key[a];
        int p2 = a - 1;
        while (p2 >= 0 && key[p2] < kk) { key[p2 + 1] = key[p2]; p2--; }
        key[p2 + 1] = kk;
    }

    int* out = g_idx + (size_t)(b * NP + n) * KK;
    int ptr = 0;
    for (int sel = 0; sel < KK; sel++) {
        unsigned long long vv = (ptr < 8) ? key[ptr] : 0ULL;
        #pragma unroll
        for (int s = 16; s > 0; s >>= 1) {
            unsigned long long o = __shfl_down_sync(0xFFFFFFFFu, vv, s);
            vv = (o > vv) ? o : vv;
        }
        if (lane == 0) swarp[warp] = vv;
        __syncthreads();
        if (warp == 0) {
            unsigned long long m = (lane < 8) ? swarp[lane] : 0ULL;
            #pragma unroll
            for (int s = 4; s > 0; s >>= 1) {
                unsigned long long o = __shfl_down_sync(0xFFFFFFFFu, m, s);
                m = (o > m) ? o : m;
            }
            if (lane == 0) {
                swin_s = m;
                out[sel] = (int)(0xFFFFFFFFu - (unsigned)(m & 0xFFFFFFFFull));
            }
        }
        __syncthreads();
        unsigned long long w = swin_s;
        if (ptr < 8 && key[ptr] == w) ptr++;
    }
}

// ---------------- edge conv: transposed weights, float4 D ----------------
template<int C, int O, int TPB>
__global__ void conv_kernel(const float* __restrict__ xin, const float* __restrict__ Wt,
                            float* __restrict__ m) {
    __shared__ __align__(16) float xc[(C + 3) & ~3];
    __shared__ __align__(16) float D[KK][(C & 3) ? C + 1 : C + 4];
    __shared__ int nidx[KK];
    const int tid = threadIdx.x;
    const int b = blockIdx.x / NP;
    const int n = blockIdx.x % NP;
    const float* xb = xin + (size_t)b * NP * C;

    for (int c = tid; c < C; c += TPB) xc[c] = xb[(size_t)n * C + c];
    if (tid < KK) nidx[tid] = g_idx[(size_t)(b * NP + n) * KK + tid];
    __syncthreads();
    for (int e = tid; e < KK * C; e += TPB) {
        int k = e / C, c = e % C;
        D[k][c] = xb[(size_t)nidx[k] * C + c] - xc[c];
    }
    __syncthreads();

    for (int o = tid; o < O; o += TPB) {
        float cx = 0.f;
        #pragma unroll 4
        for (int c = 0; c < C; c++) cx += Wt[(C + c) * O + o] * xc[c];
        float acc[KK];
        #pragma unroll
        for (int k = 0; k < KK; k++) acc[k] = cx;
        if constexpr ((C & 3) == 0) {
            for (int c = 0; c < C; c += 4) {
                float w0 = Wt[(c + 0) * O + o];
                float w1 = Wt[(c + 1) * O + o];
                float w2 = Wt[(c + 2) * O + o];
                float w3 = Wt[(c + 3) * O + o];
                #pragma unroll
                for (int k = 0; k < KK; k++) {
                    float4 d = *reinterpret_cast<const float4*>(&D[k][c]);
                    acc[k] += w0 * d.x + w1 * d.y + w2 * d.z + w3 * d.w;
                }
            }
        } else {
            for (int c = 0; c < C; c++) {
                float w = Wt[c * O + o];
                #pragma unroll
                for (int k = 0; k < KK; k++) acc[k] += w * D[k][c];
            }
        }
        float mv = -CUDART_INF_F;
        double s = 0.0, s2 = 0.0;
        #pragma unroll
        for (int k = 0; k < KK; k++) {
            mv = fmaxf(mv, acc[k]);
            s += (double)acc[k];
            s2 += (double)acc[k] * (double)acc[k];
        }
        m[(size_t)(b * NP + n) * O + o] = mv;
        atomicAdd(&g_sum[o], s);
        atomicAdd(&g_sumsq[o], s2);
    }
}

// ---------------- post: xout = lrelu(bn(m)) ----------------
template<int O>
__global__ void post_kernel(const float* __restrict__ m, const float* __restrict__ gamma,
                            const float* __restrict__ beta, float* __restrict__ xout,
                            double Minv) {
    int i = blockIdx.x * blockDim.x + threadIdx.x;
    if (i >= BN * O) return;
    int o = i % O;
    double mean = g_sum[o] * Minv;
    double var = g_sumsq[o] * Minv - mean * mean;
    float scale = (float)(1.0 / sqrt(var + (double)EPSV));
    float h = ((m[i] - (float)mean) * scale) * gamma[o] + beta[o];
    xout[i] = (h >= 0.f) ? h : SLOPEV * h;
}

// ---------------- conv5: 16 points/block, transposed W5 ----------------
__global__ void conv5_kernel() {
    __shared__ __align__(16) float sx[16][512];
    const int tid = threadIdx.x;
    const int b = blockIdx.x / (NP / 16);
    const int n0 = (blockIdx.x % (NP / 16)) * 16;

    for (int e = tid; e < 16 * 512; e += 256) {
        int p = e >> 9, c = e & 511;
        size_t pn = (size_t)b * NP + n0 + p;
        float v;
        if (c < 64)       v = g_x1[pn * 64 + c];
        else if (c < 128) v = g_x2[pn * 64 + (c - 64)];
        else if (c < 256) v = g_x3[pn * 128 + (c - 128)];
        else              v = g_x4[pn * 256 + (c - 256)];
        sx[p][c] = v;
    }
    __syncthreads();

    #pragma unroll
    for (int j = 0; j < 4; j++) {
        int o = tid + j * 256;
        float acc[16];
        #pragma unroll
        for (int p = 0; p < 16; p++) acc[p] = 0.f;
        for (int c = 0; c < 512; c += 4) {
            float w0 = g_W5t[(c + 0) * 1024 + o];
            float w1 = g_W5t[(c + 1) * 1024 + o];
            float w2 = g_W5t[(c + 2) * 1024 + o];
            float w3 = g_W5t[(c + 3) * 1024 + o];
            #pragma unroll
            for (int p = 0; p < 16; p++) {
                float4 d = *reinterpret_cast<const float4*>(&sx[p][c]);
                acc[p] += w0 * d.x + w1 * d.y + w2 * d.z + w3 * d.w;
            }
        }
        double s = 0.0, s2 = 0.0;
        float mv = -CUDART_INF_F;
        #pragma unroll
        for (int p = 0; p < 16; p++) {
            s += (double)acc[p]; s2 += (double)acc[p] * (double)acc[p];
            mv = fmaxf(mv, acc[p]);
        }
        atomicAdd(&g_sum[o], s);
        atomicAdd(&g_sumsq[o], s2);
        atomicMaxFloat(&g_m5[b * 1024 + o], mv);
    }
}

// ---------------- final: out[b][o] = lrelu(bn(max_n h5)) ----------------
__global__ void final_kernel(const float* __restrict__ g5, const float* __restrict__ b5,
                             float* __restrict__ out) {
    int b = blockIdx.x;
    int o = threadIdx.x;
    const double Minv = 1.0 / (double)(BB * NP);
    double mean = g_sum[o] * Minv;
    double var = g_sumsq[o] * Minv - mean * mean;
    float scale = (float)(1.0 / sqrt(var + (double)EPSV));
    float h = ((g_m5[b * 1024 + o] - (float)mean) * scale) * g5[o] + b5[o];
    out[b * 1024 + o] = (h >= 0.f) ? h : SLOPEV * h;
}

// ---------------- launch ----------------
extern "C" void kernel_launch(void* const* d_in, const int* in_sizes, int n_in,
                              void* d_out, int out_size) {
    const float* x  = (const float*)d_in[0];
    const float* W1 = (const float*)d_in[1];
    const float* g1 = (const float*)d_in[2];
    const float* b1 = (const float*)d_in[3];
    const float* W2 = (const float*)d_in[4];
    const float* g2 = (const float*)d_in[5];
    const float* b2 = (const float*)d_in[6];
    const float* W3 = (const float*)d_in[7];
    const float* g3 = (const float*)d_in[8];
    const float* b3 = (const float*)d_in[9];
    const float* W4 = (const float*)d_in[10];
    const float* g4 = (const float*)d_in[11];
    const float* b4 = (const float*)d_in[12];
    const float* W5 = (const float*)d_in[13];
    const float* g5 = (const float*)d_in[14];
    const float* b5 = (const float*)d_in[15];
    float* out = (float*)d_out;

    const double MinvK = 1.0 / (double)(BB * NP * KK);

    float *d_m, *d_x1, *d_x2, *d_x3, *d_x4;
    float *d_W1t, *d_W2t, *d_W3t, *d_W4t, *d_W5t;
    cudaGetSymbolAddress((void**)&d_m, g_m);
    cudaGetSymbolAddress((void**)&d_x1, g_x1);
    cudaGetSymbolAddress((void**)&d_x2, g_x2);
    cudaGetSymbolAddress((void**)&d_x3, g_x3);
    cudaGetSymbolAddress((void**)&d_x4, g_x4);
    cudaGetSymbolAddress((void**)&d_W1t, g_W1t);
    cudaGetSymbolAddress((void**)&d_W2t, g_W2t);
    cudaGetSymbolAddress((void**)&d_W3t, g_W3t);
    cudaGetSymbolAddress((void**)&d_W4t, g_W4t);
    cudaGetSymbolAddress((void**)&d_W5t, g_W5t);

    // ---- weight transposes ----
    transpose_kernel<<<(64 * 6 + 255) / 256, 256>>>(W1, d_W1t, 64, 6);
    transpose_kernel<<<(64 * 128 + 255) / 256, 256>>>(W2, d_W2t, 64, 128);
    transpose_kernel<<<(128 * 128 + 255) / 256, 256>>>(W3, d_W3t, 128, 128);
    transpose_kernel<<<(256 * 256 + 255) / 256, 256>>>(W4, d_W4t, 256, 256);
    transpose_kernel<<<(1024 * 512 + 255) / 256, 256>>>(W5, d_W5t, 1024, 512);

    dim3 pdgrid(NP / 64, BB);

    // ---- Layer 1 (C=3 -> O=64) ----
    reset_stats_kernel<<<4, 256>>>();
    xx_kernel<3><<<BN / 256, 256>>>(x);
    knn3_kernel<<<BN, 256>>>(x);
    conv_kernel<3, 64, 128><<<BN, 128>>>(x, d_W1t, d_m);
    post_kernel<64><<<(BN * 64) / 256, 256>>>(d_m, g1, b1, d_x1, MinvK);

    // ---- Layer 2 (C=64 -> O=64) ----
    reset_stats_kernel<<<4, 256>>>();
    xx_kernel<64><<<BN / 256, 256>>>(d_x1);
    pd_kernel<64><<<pdgrid, 256>>>(d_x1);
    topk_kernel<<<BN, 256>>>();
    conv_kernel<64, 64, 128><<<BN, 128>>>(d_x1, d_W2t, d_m);
    post_kernel<64><<<(BN * 64) / 256, 256>>>(d_m, g2, b2, d_x2, MinvK);

    // ---- Layer 3 (C=64 -> O=128) ----
    reset_stats_kernel<<<4, 256>>>();
    xx_kernel<64><<<BN / 256, 256>>>(d_x2);
    pd_kernel<64><<<pdgrid, 256>>>(d_x2);
    topk_kernel<<<BN, 256>>>();
    conv_kernel<64, 128, 128><<<BN, 128>>>(d_x2, d_W3t, d_m);
    post_kernel<128><<<(BN * 128) / 256, 256>>>(d_m, g3, b3, d_x3, MinvK);

    // ---- Layer 4 (C=128 -> O=256) ----
    reset_stats_kernel<<<4, 256>>>();
    xx_kernel<128><<<BN / 256, 256>>>(d_x3);
    pd_kernel<128><<<pdgrid, 256>>>(d_x3);
    topk_kernel<<<BN, 256>>>();
    conv_kernel<128, 256, 256><<<BN, 256>>>(d_x3, d_W4t, d_m);
    post_kernel<256><<<(BN * 256) / 256, 256>>>(d_m, g4, b4, d_x4, MinvK);

    // ---- conv5 + global max ----
    reset_m5_kernel<<<32, 256>>>();
    conv5_kernel<<<BB * (NP / 16), 256>>>();
    final_kernel<<<BB, 1024>>>(g5, b5, out);
}